// round 9
// baseline (speedup 1.0000x reference)
#include <cuda_runtime.h>
#include <cuda_fp16.h>
#include <cstdint>
#include <math.h>

// ---------------------------------------------------------------------------
// Problem constants
// ---------------------------------------------------------------------------
#define BATCH 4
#define SEQ   4096
#define HID   1024
#define NH    16
#define DH    64
#define M_TOT (BATCH * SEQ)   // 16384
#define N_TOT (3 * HID)       // 3072
#define K_TOT HID             // 1024

// Scratch (device globals: allocation-free rule)
__device__ __half g_qkv[(size_t)M_TOT * N_TOT];  // 96 MB
__device__ __half g_ah[(size_t)M_TOT * K_TOT];   // 32 MB
__device__ __half g_wh[(size_t)N_TOT * K_TOT];   // 6 MB

// ---------------------------------------------------------------------------
// Helpers (sm_80-era PTX only)
// ---------------------------------------------------------------------------
__device__ __forceinline__ uint32_t smem_u32(const void* p) {
    uint32_t a;
    asm("{ .reg .u64 t; cvta.to.shared.u64 t, %1; cvt.u32.u64 %0, t; }"
        : "=r"(a) : "l"(p));
    return a;
}

__device__ __forceinline__ void cp_async16(uint32_t s, const void* g) {
    asm volatile("cp.async.cg.shared.global [%0], [%1], 16;" :: "r"(s), "l"(g) : "memory");
}

__device__ __forceinline__ void ldsm_x4(uint32_t& r0, uint32_t& r1,
                                        uint32_t& r2, uint32_t& r3, uint32_t addr) {
    asm volatile("ldmatrix.sync.aligned.m8n8.x4.shared.b16 {%0,%1,%2,%3}, [%4];"
                 : "=r"(r0), "=r"(r1), "=r"(r2), "=r"(r3) : "r"(addr));
}

__device__ __forceinline__ void mma_fp16(float* c, const uint32_t* a,
                                         uint32_t b0, uint32_t b1) {
    asm volatile(
        "mma.sync.aligned.m16n8k16.row.col.f32.f16.f16.f32 "
        "{%0,%1,%2,%3}, {%4,%5,%6,%7}, {%8,%9}, {%0,%1,%2,%3};"
        : "+f"(c[0]), "+f"(c[1]), "+f"(c[2]), "+f"(c[3])
        : "r"(a[0]), "r"(a[1]), "r"(a[2]), "r"(a[3]), "r"(b0), "r"(b1));
}

// ---------------------------------------------------------------------------
// Conversion: A(fp32) -> fp16, W(fp32) -> fp16
// ---------------------------------------------------------------------------
#define N4_A ((size_t)M_TOT * K_TOT / 4)
#define N4_W ((size_t)N_TOT * K_TOT / 4)
#define N4_TOTAL (N4_A + N4_W)

__global__ __launch_bounds__(256) void convert_kernel(
    const float* __restrict__ A, const float* __restrict__ W)
{
    size_t idx = (size_t)blockIdx.x * blockDim.x + threadIdx.x;
    if (idx >= N4_TOTAL) return;

    if (idx < N4_A) {
        float4 v = ((const float4*)A)[idx];
        __half h[4] = { __float2half_rn(v.x), __float2half_rn(v.y),
                        __float2half_rn(v.z), __float2half_rn(v.w) };
        *(uint2*)(g_ah + idx * 4) = *(uint2*)h;
    } else {
        size_t j = idx - N4_A;
        float4 v = ((const float4*)W)[j];
        __half h[4] = { __float2half_rn(v.x), __float2half_rn(v.y),
                        __float2half_rn(v.z), __float2half_rn(v.w) };
        *(uint2*)(g_wh + j * 4) = *(uint2*)h;
    }
}

// ---------------------------------------------------------------------------
// GEMM fp16 single-pass: qkv[m,n] = sum_k A[m,k]*W[n,k] + bias[n]
// CTA 128x128, BK=64 (16 k-iterations), 3-stage cp.async, 2 CTAs/SM.
// Smem row = 128B data + 16B pad (144B): rows 0..7 hit distinct 16B slots
// mod 128 -> conflict-free ldmatrix; 16B-aligned cp.async.
// ---------------------------------------------------------------------------
#define BK      64
#define KITERS  (K_TOT / BK)     // 16
#define STAGES  3
#define ROWB    144              // 128B data + 16B pad
#define TILEB   (128 * ROWB)     // 18432
#define STAGEB  (2 * TILEB)      // 36864 (Ah, Wh)
#define GEMM_SMEM (STAGES * STAGEB)  // 110592 -> 2 CTAs/SM

__global__ void __launch_bounds__(256, 2) gemm_qkv_mma(
    const __half* __restrict__ Ah, const __half* __restrict__ Wh,
    const float* __restrict__ bias, __half* __restrict__ C)
{
    extern __shared__ char smem[];
    const uint32_t sb = smem_u32(smem);
    const int t    = threadIdx.x;
    const int wid  = t >> 5;
    const int lane = t & 31;
    const int m0 = blockIdx.y * 128;
    const int n0 = blockIdx.x * 128;
    const int wm = (wid & 1) * 64;
    const int wn = (wid >> 1) * 32;

    // cp.async mapping: 8 x 16B chunks per thread per stage.
    // Per tile: 128 rows x 8 chunks (128B) = 1024 chunks; 4 per thread; 2 tiles.
    const char* gptr[8];
    uint32_t    soff[8];
#pragma unroll
    for (int i = 0; i < 8; i++) {
        const int tile = i >> 2;            // 0=Ah, 1=Wh
        const int row  = (i & 3) * 32 + (t >> 3);   // 0..127
        const int c    = t & 7;                     // 16B chunk in 128B row
        const __half* base = (tile == 0) ? Ah : Wh;
        const int grow = ((tile == 0) ? m0 : n0) + row;
        gptr[i] = (const char*)(base + (size_t)grow * K_TOT) + c * 16;
        soff[i] = (uint32_t)(tile * TILEB + row * ROWB + c * 16);
    }

    auto load_stage = [&](int s) {
        const uint32_t dst = sb + (s % STAGES) * STAGEB;
        const int koff = s * (BK * 2);   // 128 bytes per k-stage
#pragma unroll
        for (int i = 0; i < 8; i++)
            cp_async16(dst + soff[i], gptr[i] + koff);
    };

    float acc[4][4][4];
#pragma unroll
    for (int mt = 0; mt < 4; mt++)
#pragma unroll
        for (int nt = 0; nt < 4; nt++)
#pragma unroll
            for (int q = 0; q < 4; q++) acc[mt][nt][q] = 0.0f;

#pragma unroll
    for (int s = 0; s < STAGES - 1; s++) {
        load_stage(s);
        asm volatile("cp.async.commit_group;" ::: "memory");
    }

    const int lrow  = lane & 15;
    const int lkoff = (lane >> 4) * 16;

    for (int kit = 0; kit < KITERS; kit++) {
        asm volatile("cp.async.wait_group %0;" :: "n"(STAGES - 2) : "memory");
        __syncthreads();

        if (kit + STAGES - 1 < KITERS) load_stage(kit + STAGES - 1);
        asm volatile("cp.async.commit_group;" ::: "memory");

        const uint32_t bufb = sb + (kit % STAGES) * STAGEB;
        const uint32_t aH = bufb;
        const uint32_t wH = bufb + TILEB;

#pragma unroll
        for (int ks = 0; ks < 4; ks++) {
            const uint32_t kb = (uint32_t)(ks * 32 + lkoff);

            uint32_t af[4][4];
#pragma unroll
            for (int mt = 0; mt < 4; mt++) {
                const uint32_t ro = (uint32_t)((wm + mt * 16 + lrow) * ROWB) + kb;
                ldsm_x4(af[mt][0], af[mt][1], af[mt][2], af[mt][3], aH + ro);
            }

            uint32_t bh0[4], bh1[4];
#pragma unroll
            for (int np = 0; np < 2; np++) {
                const uint32_t ro = (uint32_t)((wn + np * 16 + lrow) * ROWB) + kb;
                uint32_t r0, r1, r2, r3;
                ldsm_x4(r0, r1, r2, r3, wH + ro);
                bh0[np * 2] = r0; bh1[np * 2] = r2;
                bh0[np * 2 + 1] = r1; bh1[np * 2 + 1] = r3;
            }

#pragma unroll
            for (int mt = 0; mt < 4; mt++)
#pragma unroll
                for (int nt = 0; nt < 4; nt++)
                    mma_fp16(acc[mt][nt], af[mt], bh0[nt], bh1[nt]);
        }
    }

    // Epilogue: bias add + fp16 store
#pragma unroll
    for (int mt = 0; mt < 4; mt++) {
        const int r = m0 + wm + mt * 16 + (lane >> 2);
#pragma unroll
        for (int nt = 0; nt < 4; nt++) {
            const int cc = n0 + wn + nt * 8 + (lane & 3) * 2;
            const float bx = __ldg(bias + cc);
            const float by = __ldg(bias + cc + 1);
            __half2 h0, h1;
            h0.x = __float2half_rn(acc[mt][nt][0] + bx);
            h0.y = __float2half_rn(acc[mt][nt][1] + by);
            h1.x = __float2half_rn(acc[mt][nt][2] + bx);
            h1.y = __float2half_rn(acc[mt][nt][3] + by);
            *(__half2*)(C + (size_t)r * N_TOT + cc)       = h0;
            *(__half2*)(C + (size_t)(r + 8) * N_TOT + cc) = h1;
        }
    }
}

// ---------------------------------------------------------------------------
// Attention: WARP-per-position. 128-thr blocks = 4 positions. No block syncs.
// ---------------------------------------------------------------------------
__global__ __launch_bounds__(128) void attn_kernel(
    const __half* __restrict__ qkv, const float* __restrict__ mask,
    float* __restrict__ out)
{
    __shared__ __align__(16) unsigned char sm[4][8000];

    const int wid  = threadIdx.x >> 5;
    const int lane = threadIdx.x & 31;
    const int p = blockIdx.x * 4 + wid;

    __half* sqkv = (__half*)sm[wid];                 // arr*1152 + h*72 + d
    float*  sw   = (float*)(sm[wid] + 6912);         // [16][17]

    // Load 3072 halfs = 384 uint4; 12 per lane
    {
        const uint4* src = (const uint4*)(qkv + (size_t)p * N_TOT);
#pragma unroll
        for (int i = lane; i < 384; i += 32) {
            uint4 raw = src[i];
            const int e = i * 8;
            const int arr = e >> 10;          // 0=q, 1=k, 2=v
            const int r   = e & 1023;
            *(uint4*)(sqkv + arr * 1152 + (r >> 6) * 72 + (r & 63)) = raw;
        }
    }
    __syncwarp();

    const int h  = lane >> 1;
    const int gh = lane & 1;

    // ---- QK: 8 dot products of length 64 ----
    float s[8];
#pragma unroll
    for (int gi = 0; gi < 8; gi++) s[gi] = 0.0f;

    const __half* qrow = sqkv + h * 72;
#pragma unroll
    for (int d8 = 0; d8 < 8; d8++) {
        uint4 qraw = *(const uint4*)(qrow + d8 * 8);
        const __half2* qh2 = (const __half2*)&qraw;
        float qf[8];
#pragma unroll
        for (int j = 0; j < 4; j++) {
            float2 f = __half22float2(qh2[j]);
            qf[2 * j] = f.x; qf[2 * j + 1] = f.y;
        }
#pragma unroll
        for (int gi = 0; gi < 8; gi++) {
            const __half* krow = sqkv + 1152 + (gh * 8 + gi) * 72;
            uint4 kraw = *(const uint4*)(krow + d8 * 8);
            const __half2* kh2 = (const __half2*)&kraw;
#pragma unroll
            for (int j = 0; j < 4; j++) {
                float2 f = __half22float2(kh2[j]);
                s[gi] += qf[2 * j] * f.x + qf[2 * j + 1] * f.y;
            }
        }
    }

    // scale + mask
    {
        const float* mrow = mask + (size_t)p * (NH * NH) + h * NH + gh * 8;
        float4 m0 = *(const float4*)mrow;
        float4 m1 = *(const float4*)(mrow + 4);
        const float mf[8] = {m0.x, m0.y, m0.z, m0.w, m1.x, m1.y, m1.z, m1.w};
#pragma unroll
        for (int gi = 0; gi < 8; gi++) s[gi] = s[gi] * 0.125f + mf[gi];
    }

    // ---- softmax across the 16-wide row (2 lanes per row) ----
    float mx = s[0];
#pragma unroll
    for (int gi = 1; gi < 8; gi++) mx = fmaxf(mx, s[gi]);
    mx = fmaxf(mx, __shfl_xor_sync(0xffffffff, mx, 1));

    float e[8], sum = 0.0f;
#pragma unroll
    for (int gi = 0; gi < 8; gi++) { e[gi] = __expf(s[gi] - mx); sum += e[gi]; }
    sum += __shfl_xor_sync(0xffffffff, sum, 1);
    const float inv = 1.0f / sum;

#pragma unroll
    for (int gi = 0; gi < 8; gi++) sw[h * 17 + gh * 8 + gi] = e[gi] * inv;
    __syncwarp();

    // ---- PV: lane computes out[h][gh*32 .. gh*32+31] ----
    float acc[32];
#pragma unroll
    for (int d = 0; d < 32; d++) acc[d] = 0.0f;

#pragma unroll
    for (int g = 0; g < 16; g++) {
        const float wv = sw[h * 17 + g];
        const __half* vrow = sqkv + 2304 + g * 72 + gh * 32;
#pragma unroll
        for (int d8 = 0; d8 < 4; d8++) {
            uint4 vr = *(const uint4*)(vrow + d8 * 8);
            const __half2* vh2 = (const __half2*)&vr;
#pragma unroll
            for (int j = 0; j < 4; j++) {
                float2 f = __half22float2(vh2[j]);
                acc[d8 * 8 + 2 * j]     += wv * f.x;
                acc[d8 * 8 + 2 * j + 1] += wv * f.y;
            }
        }
    }

    float* orow = out + (size_t)p * HID + h * DH + gh * 32;
#pragma unroll
    for (int d4 = 0; d4 < 8; d4++) {
        float4 o;
        o.x = acc[4 * d4]; o.y = acc[4 * d4 + 1];
        o.z = acc[4 * d4 + 2]; o.w = acc[4 * d4 + 3];
        *(float4*)(orow + 4 * d4) = o;
    }
}

// ---------------------------------------------------------------------------
// Launch — inputs: 0=query, 1=key, 2=value, 3=attn_mask, 4=W_qkv, 5=b_qkv
// ---------------------------------------------------------------------------
extern "C" void kernel_launch(void* const* d_in, const int* in_sizes, int n_in,
                              void* d_out, int out_size)
{
    const float* query = (const float*)d_in[0];
    const float* mask  = (const float*)d_in[3];
    const float* W     = (const float*)d_in[4];
    const float* bias  = (const float*)d_in[5];
    float* out = (float*)d_out;

    __half *qkv, *ah, *wh;
    cudaGetSymbolAddress((void**)&qkv, g_qkv);
    cudaGetSymbolAddress((void**)&ah, g_ah);
    cudaGetSymbolAddress((void**)&wh, g_wh);

    const int cvt_blocks = (int)((N4_TOTAL + 255) / 256);
    convert_kernel<<<cvt_blocks, 256>>>(query, W);

    cudaFuncSetAttribute(gemm_qkv_mma, cudaFuncAttributeMaxDynamicSharedMemorySize,
                         GEMM_SMEM);
    dim3 ggrid(N_TOT / 128, M_TOT / 128);  // (24, 128)
    gemm_qkv_mma<<<ggrid, 256, GEMM_SMEM>>>(ah, wh, bias, qkv);

    attn_kernel<<<M_TOT / 4, 128>>>(qkv, mask, out);
}